// round 14
// baseline (speedup 1.0000x reference)
#include <cuda_runtime.h>
#include <cuda_fp16.h>
#include <cstdint>
#include <cstddef>

// Problem constants
#define BATCH 64
#define TT    512
#define HH    1024
#define NB    256      // 128 layer-0 CTAs (A: f0,b0) + 128 layer-1 CTAs (B: f1,b1)
#define NTHR  256      // 8 warps: 2 k-halves x (2m x 2n grid of 32x32 tiles)
#define KC    128      // K-chunk (halves)
#define NCHUNK 16      // 2048 / 128
#define NSTAGE 3
#define RSB   272      // smem row stride bytes (256 + 16 pad; 17*16B -> conflict-free)
#define AREG  17408    // A region bytes within stage (64*272)
#define STAGEB 34816   // A + W regions
#define SMEM_BYTES (NSTAGE * STAGEB)   // 104448 -> 2 CTAs/SM
#define BH    (BATCH * HH)

// ---------------- device scratch ----------------
static __device__ __half g_W[(size_t)4 * 4096 * 2048];   // fused+permuted weights fp16 (64 MB)
static __device__ float  g_bias[4 * 4096];               // bih+bhh fused, permuted
static __device__ __half g_x16[(size_t)TT * BH];         // x as [t][b][k] fp16 (64 MB)
static __device__ __half g_h0[4][BH];                    // layer0 backward h, depth-4 ring
static __device__ __half g_hf0[4][BH];                   // layer0 forward h, depth-4 ring
static __device__ float  g_c0[2][BH];                    // layer0 c (internal to A)
static __device__ __half g_h1[2][BH];                    // layer1 h (internal to B)
static __device__ float  g_c1[2][BH];
static __device__ unsigned g_cnt[8 * 32];                // hierarchical barrier: 8 padded groups
static __device__ unsigned g_rootA, g_rootB;
static __device__ unsigned g_genA, g_genB;               // published step counters

// ---------------- PTX helpers ----------------
__device__ __forceinline__ uint32_t smem_u32(const void* p) {
    uint32_t a;
    asm("{ .reg .u64 t; cvta.to.shared.u64 t, %1; cvt.u32.u64 %0, t; }" : "=r"(a) : "l"(p));
    return a;
}
__device__ __forceinline__ void cp16(uint32_t saddr, const void* gptr) {
    asm volatile("cp.async.cg.shared.global [%0], [%1], 16;\n" :: "r"(saddr), "l"(gptr));
}
__device__ __forceinline__ void cp_commit() {
    asm volatile("cp.async.commit_group;\n" ::: "memory");
}
__device__ __forceinline__ void cp_wait1() {
    asm volatile("cp.async.wait_group 1;\n" ::: "memory");
}
__device__ __forceinline__ void cp_wait0() {
    asm volatile("cp.async.wait_group 0;\n" ::: "memory");
}
__device__ __forceinline__ void ldsm4(uint32_t* r, uint32_t addr) {
    asm volatile("ldmatrix.sync.aligned.m8n8.x4.shared.b16 {%0,%1,%2,%3}, [%4];"
                 : "=r"(r[0]), "=r"(r[1]), "=r"(r[2]), "=r"(r[3]) : "r"(addr));
}
__device__ __forceinline__ void mma16816(float* d, const uint32_t* a, const uint32_t* b) {
    asm volatile(
        "mma.sync.aligned.m16n8k16.row.col.f32.f16.f16.f32 "
        "{%0,%1,%2,%3}, {%4,%5,%6,%7}, {%8,%9}, {%0,%1,%2,%3};\n"
        : "+f"(d[0]), "+f"(d[1]), "+f"(d[2]), "+f"(d[3])
        : "r"(a[0]), "r"(a[1]), "r"(a[2]), "r"(a[3]), "r"(b[0]), "r"(b[1]));
}

// Wait until *f >= tgt (one thread spins, then block sync).
__device__ __forceinline__ void waitflag(volatile unsigned* f, unsigned tgt) {
    if (threadIdx.x == 0) { while (*f < tgt) { } }
    __syncthreads();
}

// Per-side hierarchical barrier: 4 groups of 32 CTAs -> root of 4 -> gen flag.
__device__ __forceinline__ void groupbar(unsigned target, bool isA) {
    __syncthreads();
    __threadfence();
    if (threadIdx.x == 0) {
        const int g = blockIdx.x >> 5;                    // A: 0..3, B: 4..7
        unsigned v = atomicAdd(&g_cnt[g * 32], 1u) + 1u;
        if (v == 32u * target) {
            unsigned r = atomicAdd(isA ? &g_rootA : &g_rootB, 1u) + 1u;
            if (r == 4u * target)
                atomicExch(isA ? &g_genA : &g_genB, target);
        }
        volatile unsigned* vg = isA ? &g_genA : &g_genB;
        while (*vg < target) { }
    }
    __syncthreads();
}

// ---------------- merged preprocessing ----------------
// Weights: g_W[gm][n'][k]; n' = nct*64 + gate*16 + u (nct 0..63 owns 16 units x 4 gates);
// k<1024 from Wih (K-reversed for gm==1, folding x's feature reversal), else Whh.
__global__ void k_prep(const float* __restrict__ x,
                       const float* __restrict__ Wih_f, const float* __restrict__ Whh_f,
                       const float* __restrict__ bih_f, const float* __restrict__ bhh_f,
                       const float* __restrict__ Wih_b, const float* __restrict__ Whh_b,
                       const float* __restrict__ bih_b, const float* __restrict__ bhh_b) {
    const size_t gstride = (size_t)gridDim.x * blockDim.x;
    const size_t gtid = (size_t)blockIdx.x * blockDim.x + threadIdx.x;

    const size_t wtotal = (size_t)4 * 4096 * 2048;
    for (size_t idx = gtid; idx < wtotal; idx += gstride) {
        int k  = (int)(idx & 2047);
        int np = (int)((idx >> 11) & 4095);
        int gm = (int)(idx >> 23);
        int loc  = np & 63;
        int nct  = np >> 6;
        int gate = loc >> 4;
        int u    = loc & 15;
        int n = gate * 1024 + nct * 16 + u;
        int layer = gm >> 1;
        bool bwd  = (gm & 1) != 0;
        const float* Wih = bwd ? Wih_b : Wih_f;
        const float* Whh = bwd ? Whh_b : Whh_f;
        float v;
        if (k < 1024) {
            int kk = (gm == 1) ? (1023 - k) : k;
            v = Wih[((size_t)layer * 4096 + n) * 1024 + kk];
        } else {
            v = Whh[((size_t)layer * 4096 + n) * 1024 + (k - 1024)];
        }
        g_W[idx] = __float2half_rn(v);
    }
    const size_t xtotal = (size_t)TT * BH;
    for (size_t idx = gtid; idx < xtotal; idx += gstride) {
        int k = (int)(idx & 1023);
        int b = (int)((idx >> 10) & 63);
        int t = (int)(idx >> 16);
        g_x16[idx] = __float2half_rn(x[((size_t)b * TT + t) * HH + k]);
    }
    for (size_t idx = gtid; idx < 16384; idx += gstride) {
        int np = (int)(idx & 4095), gm = (int)(idx >> 12);
        int loc = np & 63, nct = np >> 6;
        int gate = loc >> 4, u = loc & 15;
        int n = gate * 1024 + nct * 16 + u;
        int layer = gm >> 1;
        bool bwd = (gm & 1) != 0;
        const float* bi = bwd ? bih_b : bih_f;
        const float* bh = bwd ? bhh_b : bhh_f;
        g_bias[idx] = bi[layer * 4096 + n] + bh[layer * 4096 + n];
    }
    for (size_t idx = gtid; idx < 4 * BH; idx += gstride) {
        ((unsigned short*)g_h0)[idx]  = 0;
        ((unsigned short*)g_hf0)[idx] = 0;
    }
    for (size_t idx = gtid; idx < 2 * BH; idx += gstride) {
        ((unsigned short*)g_h1)[idx] = 0;
        ((float*)g_c0)[idx] = 0.f;
        ((float*)g_c1)[idx] = 0.f;
    }
    for (size_t idx = gtid; idx < 8 * 32; idx += gstride) g_cnt[idx] = 0u;
    if (gtid == 0) { g_rootA = 0u; g_rootB = 0u; g_genA = 0u; g_genB = 0u; }
}

// ---------------- chunk loaders (256 threads; KC=128 -> 4 ops each) ----------------
__device__ __forceinline__ void load_A(uint32_t stb, int nk, const __half* a1,
                                       const __half* a2, int tid) {
    const int koff = nk * KC;
    const __half* ap = (koff < 1024) ? (a1 + koff) : (a2 + (koff - 1024));
    #pragma unroll
    for (int j = 0; j < 4; ++j) {
        int idx = tid + j * NTHR;           // 1024 ops: 64 rows x 16 segs
        int row = idx >> 4, seg = idx & 15;
        cp16(stb + row * RSB + seg * 16, ap + row * HH + seg * 8);
    }
}
__device__ __forceinline__ void load_W(uint32_t stb, int nk, const __half* wbase, int tid) {
    const __half* wp = wbase + nk * KC;
    #pragma unroll
    for (int j = 0; j < 4; ++j) {
        int idx = tid + j * NTHR;           // 1024 ops: 64 rows x 16 segs
        int row = idx >> 4, seg = idx & 15;
        cp16(stb + AREG + row * RSB + seg * 16, wp + (size_t)row * 2048 + seg * 8);
    }
}

// ---------------- persistent LSTM kernel (decoupled layer pipelines) ----------------
// 256 CTAs (2/SM). gm = blockIdx.x>>6 in {f0,b0,f1,b1}; nct = blockIdx.x&63 owns 64 N-cols.
// Side A (gm<2) runs layer0 t=0..511 with its own 128-CTA barrier; side B (gm>=2) runs
// layer1, consuming A's depth-4 h0/hf0 rings via flags (slack 3 steps, backpressured).
__global__ void __launch_bounds__(NTHR, 2) k_lstm(float* __restrict__ dout) {
    extern __shared__ __align__(16) unsigned char sm[];
    const uint32_t smb = smem_u32(sm);
    float* gsm  = (float*)sm;                // overlay: stage0 A region (k-half 0 gates)
    float* gsm2 = (float*)(sm + STAGEB);     // overlay: stage1 A region (k-half 1 gates)

    const int tid  = threadIdx.x;
    const int lane = tid & 31;
    const int warp = tid >> 5;
    const int grp  = warp >> 2;             // k-half of each chunk
    const int w4   = warp & 3;
    const int m0 = (w4 >> 1) * 32;          // 2m x 2n grid of 32x32 warp tiles
    const int n0 = (w4 & 1) * 32;
    const int gm   = blockIdx.x >> 6;
    const int nct  = blockIdx.x & 63;
    const bool isA = (gm < 2);
    const uint32_t khB = (uint32_t)(grp * 128);   // byte offset of this warp's k-half

    const __half* wbase = g_W + ((size_t)(gm * 4096 + nct * 64)) * 2048;
    const float*  bp    = g_bias + gm * 4096 + nct * 64;

    float* out   = dout;
    float* cout  = dout + (size_t)67108864;   // B*T*2H
    float* outL  = dout + (size_t)134217728;  // 2*B*T*2H
    float* coutL = outL + 131072;             // B*2H

    // ldmatrix per-lane base offsets (bytes)
    const int mat = lane >> 3, mr = lane & 7;
    const uint32_t aoffL = (uint32_t)((m0 + (mat & 1) * 8 + mr) * RSB + (mat >> 1) * 16);
    const uint32_t woffL = (uint32_t)((n0 + (mat >> 1) * 8 + mr) * RSB + (mat & 1) * 16);

    // pre-loop: prefetch W chunks 0,1 into stages 0,1
    load_W(smb,          0, wbase, tid); cp_commit();
    load_W(smb + STAGEB, 1, wbase, tid); cp_commit();

    #pragma unroll 1
    for (int t = 0; t < TT; ++t) {
        // B consumes A's step-t outputs: wait for A to publish step t
        if (!isA) waitflag(&g_genA, (unsigned)(t + 1));

        const __half* a1;
        const __half* a2;
        if (isA)           { a1 = g_x16 + (size_t)t * BH;  a2 = g_h0[(t + 3) & 3]; }
        else if (gm == 2)  { a1 = g_hf0[t & 3];            a2 = g_h1[(t + 1) & 1]; }
        else               { a1 = g_h0[t & 3];             a2 = g_h1[(t + 1) & 1]; }

        // A for chunks 0,1 (W already prefetched)
        load_A(smb,          0, a1, a2, tid); cp_commit();
        load_A(smb + STAGEB, 1, a1, a2, tid); cp_commit();

        // prefetch c_prev for this thread's 4 epilogue items
        float cpre[4];
        {
            const float* cb = (isA ? g_c0 : g_c1)[(t + 1) & 1];
            #pragma unroll
            for (int j = 0; j < 4; ++j) {
                int idx = tid + j * NTHR;
                int bb = idx >> 4, ul = idx & 15;
                cpre[j] = __ldcg(&cb[bb * HH + nct * 16 + ul]);
            }
        }

        float acc[2][4][4];
        #pragma unroll
        for (int a = 0; a < 2; ++a)
            #pragma unroll
            for (int b = 0; b < 4; ++b)
                #pragma unroll
                for (int c = 0; c < 4; ++c) acc[a][b][c] = 0.f;

        // ---- K loop: 16 chunks of KC=128, 3-stage cp.async ring ----
        #pragma unroll 1
        for (int kc = 0; kc < NCHUNK; ++kc) {
            cp_wait1();        // chunk kc fully landed (only chunk kc+1's group younger)
            __syncthreads();   // all warps done with chunk kc-1; its stage reusable
            {
                const int nk = kc + 2;
                if (nk < NCHUNK) {
                    uint32_t stb = smb + (nk % 3) * STAGEB;
                    load_A(stb, nk, a1, a2, tid);
                    load_W(stb, nk, wbase, tid);
                }
                cp_commit();   // always commit (uniform group counts)
            }
            const uint32_t Ab = smb + (kc % 3) * STAGEB;
            const uint32_t Wb = Ab + AREG;
            uint32_t af[2][2][4], bf[2][2][4];
            ldsm4(af[0][0], Ab + aoffL + khB);
            ldsm4(af[0][1], Ab + aoffL + 4352 + khB);
            ldsm4(bf[0][0], Wb + woffL + khB);
            ldsm4(bf[0][1], Wb + woffL + 4352 + khB);
            #pragma unroll
            for (int ks = 0; ks < 4; ++ks) {
                const int cb = ks & 1, nb = cb ^ 1;
                if (ks < 3) {
                    const uint32_t ko = khB + (uint32_t)((ks + 1) * 32);
                    ldsm4(af[nb][0], Ab + aoffL + ko);
                    ldsm4(af[nb][1], Ab + aoffL + 4352 + ko);
                    ldsm4(bf[nb][0], Wb + woffL + ko);
                    ldsm4(bf[nb][1], Wb + woffL + 4352 + ko);
                }
                #pragma unroll
                for (int mt = 0; mt < 2; ++mt)
                    #pragma unroll
                    for (int nt = 0; nt < 4; ++nt)
                        mma16816(acc[mt][nt], af[ks & 1][mt], &bf[ks & 1][nt >> 1][(nt & 1) * 2]);
            }
        }
        __syncthreads();  // all stage reads done (gate overlays now safe to write)

        // prefetch next iteration's W chunks 0,1 (W regions only; overlaps tail)
        load_W(smb,          0, wbase, tid); cp_commit();
        load_W(smb + STAGEB, 1, wbase, tid); cp_commit();

        // ---- combine k-halves: grp0 -> gsm, grp1 -> gsm2; single sync ----
        {
            float* gdst = grp ? gsm2 : gsm;
            #pragma unroll
            for (int mt = 0; mt < 2; ++mt)
                #pragma unroll
                for (int nt = 0; nt < 4; ++nt)
                    #pragma unroll
                    for (int r = 0; r < 4; ++r) {
                        int row = m0 + mt * 16 + (lane >> 2) + ((r & 2) ? 8 : 0);
                        int col = n0 + nt * 8 + ((lane & 3) << 1) + (r & 1);
                        gdst[row * 68 + col] = acc[mt][nt][r];
                    }
        }
        __syncthreads();

        // A backpressure: before overwriting ring slot t&3, layer1 must have consumed t-4
        if (isA && t >= 4) waitflag(&g_genB, (unsigned)(t - 3));

        // ---- cell epilogue: 64 batches x 16 hidden units (4 per thread) ----
        #pragma unroll
        for (int j = 0; j < 4; ++j) {
            int idx = tid + j * NTHR;
            int bb = idx >> 4, ul = idx & 15;
            int uglob = nct * 16 + ul;
            int s = bb * HH + uglob;
            float gi = gsm[bb * 68 + ul]      + gsm2[bb * 68 + ul]      + bp[ul];
            float gf = gsm[bb * 68 + 16 + ul] + gsm2[bb * 68 + 16 + ul] + bp[16 + ul];
            float gg = gsm[bb * 68 + 32 + ul] + gsm2[bb * 68 + 32 + ul] + bp[32 + ul];
            float go = gsm[bb * 68 + 48 + ul] + gsm2[bb * 68 + 48 + ul] + bp[48 + ul];
            float si = 1.f / (1.f + __expf(-gi));
            float sf = 1.f / (1.f + __expf(-gf));
            float so = 1.f / (1.f + __expf(-go));
            float tg = tanhf(gg);
            float cn = sf * cpre[j] + si * tg;
            float h  = so * tanhf(cn);
            if (gm == 0) {
                g_hf0[t & 3][s] = __float2half_rn(h);
            } else if (gm == 1) {
                g_h0[t & 3][s] = __float2half_rn(h);
                g_c0[t & 1][s] = cn;
            } else {
                size_t ob = ((size_t)bb * TT + t) * 2048 + (gm == 3 ? 1024 : 0) + uglob;
                out[ob]  = h;
                cout[ob] = cn;
                if (t == TT - 1) {
                    int o2 = bb * 2048 + (gm == 3 ? 1024 : 0) + uglob;
                    outL[o2]  = h;
                    coutL[o2] = cn;
                }
                if (gm == 3) {
                    g_h1[t & 1][s] = __float2half_rn(h);
                    g_c1[t & 1][s] = cn;
                }
            }
        }
        groupbar((unsigned)(t + 1), isA);
    }
    cp_wait0();   // drain leftover W prefetch before exit
}

// ---------------- launcher ----------------
extern "C" void kernel_launch(void* const* d_in, const int* in_sizes, int n_in,
                              void* d_out, int out_size) {
    (void)in_sizes; (void)n_in; (void)out_size;
    const float* x     = (const float*)d_in[0];
    const float* Wih_f = (const float*)d_in[1];
    const float* Whh_f = (const float*)d_in[2];
    const float* bih_f = (const float*)d_in[3];
    const float* bhh_f = (const float*)d_in[4];
    const float* Wih_b = (const float*)d_in[5];
    const float* Whh_b = (const float*)d_in[6];
    const float* bih_b = (const float*)d_in[7];
    const float* bhh_b = (const float*)d_in[8];

    cudaFuncSetAttribute(k_lstm, cudaFuncAttributeMaxDynamicSharedMemorySize, SMEM_BYTES);

    k_prep<<<8192, 256>>>(x, Wih_f, Whh_f, bih_f, bhh_f, Wih_b, Whh_b, bih_b, bhh_b);
    k_lstm<<<NB, NTHR, SMEM_BYTES>>>((float*)d_out);
}

// round 15
// speedup vs baseline: 1.0624x; 1.0624x over previous
#include <cuda_runtime.h>
#include <cuda_fp16.h>
#include <cstdint>
#include <cstddef>

// Problem constants
#define BATCH 64
#define TT    512
#define HH    1024
#define NB    256      // 128 layer-0 CTAs (A: f0,b0) + 128 layer-1 CTAs (B: f1,b1)
#define NTHR  256      // 8 warps: 2 k-halves x (2m x 2n grid of 32x32 tiles)
#define KC    64       // K-chunk (halves)
#define NCHUNK 32      // 2048 / 64
#define NSTAGE 4
#define STAGEB 18432   // (64 A + 64 W) rows * 144B
#define AREG   9216    // A region bytes within stage (64*144)
#define GSMO   (NSTAGE * STAGEB)              // 73728
#define GOVL   (64 * 68 * 4)                  // 17408: one gate overlay
#define SMEM_BYTES (GSMO + 2 * GOVL)          // 108544 -> 2 CTAs/SM
#define BH    (BATCH * HH)

// ---------------- device scratch ----------------
static __device__ __half g_W[(size_t)4 * 4096 * 2048];   // fused+permuted weights fp16 (64 MB)
static __device__ float  g_bias[4 * 4096];               // bih+bhh fused, permuted
static __device__ __half g_x16[(size_t)TT * BH];         // x as [t][b][k] fp16 (64 MB)
static __device__ __half g_h0[4][BH];                    // layer0 backward h, depth-4 ring
static __device__ __half g_hf0[4][BH];                   // layer0 forward h, depth-4 ring
static __device__ float  g_c0[2][BH];                    // layer0 c (A-internal)
static __device__ __half g_h1[2][BH];                    // layer1 h (B-internal)
static __device__ float  g_c1[2][BH];
static __device__ unsigned g_cnt[8 * 32];                // hierarchical barriers: 8 padded groups
static __device__ unsigned g_rootA, g_rootB;
static __device__ unsigned g_genA, g_genB;               // published step counters

// ---------------- PTX helpers ----------------
__device__ __forceinline__ uint32_t smem_u32(const void* p) {
    uint32_t a;
    asm("{ .reg .u64 t; cvta.to.shared.u64 t, %1; cvt.u32.u64 %0, t; }" : "=r"(a) : "l"(p));
    return a;
}
__device__ __forceinline__ void cp16(uint32_t saddr, const void* gptr) {
    asm volatile("cp.async.cg.shared.global [%0], [%1], 16;\n" :: "r"(saddr), "l"(gptr));
}
__device__ __forceinline__ void cp_commit() {
    asm volatile("cp.async.commit_group;\n" ::: "memory");
}
__device__ __forceinline__ void cp_wait2() {
    asm volatile("cp.async.wait_group 2;\n" ::: "memory");
}
__device__ __forceinline__ void cp_wait0() {
    asm volatile("cp.async.wait_group 0;\n" ::: "memory");
}
__device__ __forceinline__ void ldsm4(uint32_t* r, uint32_t addr) {
    asm volatile("ldmatrix.sync.aligned.m8n8.x4.shared.b16 {%0,%1,%2,%3}, [%4];"
                 : "=r"(r[0]), "=r"(r[1]), "=r"(r[2]), "=r"(r[3]) : "r"(addr));
}
__device__ __forceinline__ void mma16816(float* d, const uint32_t* a, const uint32_t* b) {
    asm volatile(
        "mma.sync.aligned.m16n8k16.row.col.f32.f16.f16.f32 "
        "{%0,%1,%2,%3}, {%4,%5,%6,%7}, {%8,%9}, {%0,%1,%2,%3};\n"
        : "+f"(d[0]), "+f"(d[1]), "+f"(d[2]), "+f"(d[3])
        : "r"(a[0]), "r"(a[1]), "r"(a[2]), "r"(a[3]), "r"(b[0]), "r"(b[1]));
}

// Wait until *f >= tgt (one thread spins, then block sync).
__device__ __forceinline__ void waitflag(volatile unsigned* f, unsigned tgt) {
    if (threadIdx.x == 0) { while (*f < tgt) { } }
    __syncthreads();
}

// Per-side hierarchical barrier: 4 groups of 32 CTAs -> root of 4 -> gen flag.
__device__ __forceinline__ void groupbar(unsigned target, bool isA) {
    __syncthreads();
    __threadfence();
    if (threadIdx.x == 0) {
        const int g = blockIdx.x >> 5;                    // A: 0..3, B: 4..7
        unsigned v = atomicAdd(&g_cnt[g * 32], 1u) + 1u;
        if (v == 32u * target) {
            unsigned r = atomicAdd(isA ? &g_rootA : &g_rootB, 1u) + 1u;
            if (r == 4u * target)
                atomicExch(isA ? &g_genA : &g_genB, target);
        }
        volatile unsigned* vg = isA ? &g_genA : &g_genB;
        while (*vg < target) { }
    }
    __syncthreads();
}

// ---------------- merged preprocessing ----------------
// Weights: g_W[gm][n'][k]; n' = nct*64 + gate*16 + u (nct 0..63 owns 16 units x 4 gates);
// k<1024 from Wih (K-reversed for gm==1, folding x's feature reversal), else Whh.
__global__ void k_prep(const float* __restrict__ x,
                       const float* __restrict__ Wih_f, const float* __restrict__ Whh_f,
                       const float* __restrict__ bih_f, const float* __restrict__ bhh_f,
                       const float* __restrict__ Wih_b, const float* __restrict__ Whh_b,
                       const float* __restrict__ bih_b, const float* __restrict__ bhh_b) {
    const size_t gstride = (size_t)gridDim.x * blockDim.x;
    const size_t gtid = (size_t)blockIdx.x * blockDim.x + threadIdx.x;

    const size_t wtotal = (size_t)4 * 4096 * 2048;
    for (size_t idx = gtid; idx < wtotal; idx += gstride) {
        int k  = (int)(idx & 2047);
        int np = (int)((idx >> 11) & 4095);
        int gm = (int)(idx >> 23);
        int loc  = np & 63;
        int nct  = np >> 6;
        int gate = loc >> 4;
        int u    = loc & 15;
        int n = gate * 1024 + nct * 16 + u;
        int layer = gm >> 1;
        bool bwd  = (gm & 1) != 0;
        const float* Wih = bwd ? Wih_b : Wih_f;
        const float* Whh = bwd ? Whh_b : Whh_f;
        float v;
        if (k < 1024) {
            int kk = (gm == 1) ? (1023 - k) : k;
            v = Wih[((size_t)layer * 4096 + n) * 1024 + kk];
        } else {
            v = Whh[((size_t)layer * 4096 + n) * 1024 + (k - 1024)];
        }
        g_W[idx] = __float2half_rn(v);
    }
    const size_t xtotal = (size_t)TT * BH;
    for (size_t idx = gtid; idx < xtotal; idx += gstride) {
        int k = (int)(idx & 1023);
        int b = (int)((idx >> 10) & 63);
        int t = (int)(idx >> 16);
        g_x16[idx] = __float2half_rn(x[((size_t)b * TT + t) * HH + k]);
    }
    for (size_t idx = gtid; idx < 16384; idx += gstride) {
        int np = (int)(idx & 4095), gm = (int)(idx >> 12);
        int loc = np & 63, nct = np >> 6;
        int gate = loc >> 4, u = loc & 15;
        int n = gate * 1024 + nct * 16 + u;
        int layer = gm >> 1;
        bool bwd = (gm & 1) != 0;
        const float* bi = bwd ? bih_b : bih_f;
        const float* bh = bwd ? bhh_b : bhh_f;
        g_bias[idx] = bi[layer * 4096 + n] + bh[layer * 4096 + n];
    }
    for (size_t idx = gtid; idx < 4 * BH; idx += gstride) {
        ((unsigned short*)g_h0)[idx]  = 0;
        ((unsigned short*)g_hf0)[idx] = 0;
    }
    for (size_t idx = gtid; idx < 2 * BH; idx += gstride) {
        ((unsigned short*)g_h1)[idx] = 0;
        ((float*)g_c0)[idx] = 0.f;
        ((float*)g_c1)[idx] = 0.f;
    }
    for (size_t idx = gtid; idx < 8 * 32; idx += gstride) g_cnt[idx] = 0u;
    if (gtid == 0) { g_rootA = 0u; g_rootB = 0u; g_genA = 0u; g_genB = 0u; }
}

// ---------------- chunk loaders (KC=64: 2 ops/thread each) ----------------
__device__ __forceinline__ void load_A(uint32_t stb, int nk, const __half* a1,
                                       const __half* a2, int tid) {
    const int koff = nk * KC;
    const __half* ap = (koff < 1024) ? (a1 + koff) : (a2 + (koff - 1024));
    #pragma unroll
    for (int j = 0; j < 2; ++j) {
        int idx = tid + j * NTHR;           // 512 ops: 64 rows x 8 segs
        int row = idx >> 3, seg = idx & 7;
        cp16(stb + row * 144 + seg * 16, ap + row * HH + seg * 8);
    }
}
__device__ __forceinline__ void load_W(uint32_t stb, int nk, const __half* wbase, int tid) {
    const __half* wp = wbase + nk * KC;
    #pragma unroll
    for (int j = 0; j < 2; ++j) {
        int idx = tid + j * NTHR;           // 512 ops: 64 rows x 8 segs
        int row = idx >> 3, seg = idx & 7;
        cp16(stb + AREG + row * 144 + seg * 16, wp + (size_t)row * 2048 + seg * 8);
    }
}

// ---------------- persistent LSTM kernel (decoupled layer pipelines) ----------------
// 256 CTAs (2/SM). gm = blockIdx.x>>6 in {f0,b0,f1,b1}; nct = blockIdx.x&63 owns 64 N-cols.
// Side A (gm<2) runs layer0 with its own 128-CTA barrier; side B (gm>=2) runs layer1,
// consuming A's depth-4 h0/hf0 rings via flags (slack 3 steps, backpressured).
__global__ void __launch_bounds__(NTHR, 2) k_lstm(float* __restrict__ dout) {
    extern __shared__ __align__(16) unsigned char sm[];
    const uint32_t smb = smem_u32(sm);
    float* gsm  = (float*)(sm + GSMO);          // gate overlay, k-half 0
    float* gsm2 = (float*)(sm + GSMO + GOVL);   // gate overlay, k-half 1

    const int tid  = threadIdx.x;
    const int lane = tid & 31;
    const int warp = tid >> 5;
    const int grp  = warp >> 2;             // k-half: 0 -> k 0..31, 1 -> k 32..63 of chunk
    const int w4   = warp & 3;
    const int m0 = (w4 >> 1) * 32;          // 2m x 2n grid of 32x32 warp tiles
    const int n0 = (w4 & 1) * 32;
    const int gm   = blockIdx.x >> 6;
    const int nct  = blockIdx.x & 63;
    const bool isA = (gm < 2);
    const uint32_t khB = (uint32_t)(grp * 64);   // byte offset of this warp's k-half

    const __half* wbase = g_W + ((size_t)(gm * 4096 + nct * 64)) * 2048;
    const float*  bp    = g_bias + gm * 4096 + nct * 64;

    float* out   = dout;
    float* cout  = dout + (size_t)67108864;   // B*T*2H
    float* outL  = dout + (size_t)134217728;  // 2*B*T*2H
    float* coutL = outL + 131072;             // B*2H

    // ldmatrix per-lane base offsets (bytes)
    const int mat = lane >> 3, mr = lane & 7;
    const uint32_t aoffL = (uint32_t)((m0 + (mat & 1) * 8 + mr) * 144 + (mat >> 1) * 16);
    const uint32_t woffL = (uint32_t)((n0 + (mat >> 1) * 8 + mr) * 144 + (mat & 1) * 16);

    // pre-loop: prefetch W chunks 0..2 into stages 0..2
    #pragma unroll
    for (int pc = 0; pc < 3; ++pc) { load_W(smb + pc * STAGEB, pc, wbase, tid); cp_commit(); }

    #pragma unroll 1
    for (int t = 0; t < TT; ++t) {
        // B consumes A's step-t outputs: wait for A to publish step t
        if (!isA) waitflag(&g_genA, (unsigned)(t + 1));

        const __half* a1;
        const __half* a2;
        if (isA)          { a1 = g_x16 + (size_t)t * BH;  a2 = g_h0[(t + 3) & 3]; }
        else if (gm == 2) { a1 = g_hf0[t & 3];            a2 = g_h1[(t + 1) & 1]; }
        else              { a1 = g_h0[t & 3];             a2 = g_h1[(t + 1) & 1]; }

        // prefetch c_prev for this thread's 4 epilogue items
        float cpre[4];
        {
            const float* cb = (isA ? g_c0 : g_c1)[(t + 1) & 1];
            #pragma unroll
            for (int j = 0; j < 4; ++j) {
                int idx = tid + j * NTHR;
                int bb = idx >> 4, ul = idx & 15;
                cpre[j] = __ldcg(&cb[bb * HH + nct * 16 + ul]);
            }
        }

        // A for chunks 0..2 (W already prefetched before the barrier)
        #pragma unroll
        for (int pc = 0; pc < 3; ++pc) { load_A(smb + pc * STAGEB, pc, a1, a2, tid); cp_commit(); }

        float acc[2][4][4];
        #pragma unroll
        for (int a = 0; a < 2; ++a)
            #pragma unroll
            for (int b = 0; b < 4; ++b)
                #pragma unroll
                for (int c = 0; c < 4; ++c) acc[a][b][c] = 0.f;

        // ---- K loop: 32 chunks, 4-stage cp.async pipeline ----
        #pragma unroll 1
        for (int kc = 0; kc < NCHUNK; ++kc) {
            cp_wait2();        // chunk kc fully landed (A+W)
            __syncthreads();   // all warps done with mma(kc-1); stage (kc-1)&3 reusable
            {
                const int nk = kc + 3;
                if (nk < NCHUNK) {
                    uint32_t stb = smb + (nk & 3) * STAGEB;
                    load_A(stb, nk, a1, a2, tid);
                    load_W(stb, nk, wbase, tid);
                }
                cp_commit();   // always commit (uniform group counts)
            }
            const uint32_t Ab = smb + (kc & 3) * STAGEB;
            const uint32_t Wb = Ab + AREG;
            uint32_t af[2][2][4], bf[2][2][4];
            #pragma unroll
            for (int ks = 0; ks < 2; ++ks) {
                ldsm4(af[ks][0], Ab + aoffL + khB + ks * 32);
                ldsm4(af[ks][1], Ab + aoffL + 2304 + khB + ks * 32);
                ldsm4(bf[ks][0], Wb + woffL + khB + ks * 32);
                ldsm4(bf[ks][1], Wb + woffL + 2304 + khB + ks * 32);
            }
            #pragma unroll
            for (int ks = 0; ks < 2; ++ks)
                #pragma unroll
                for (int mt = 0; mt < 2; ++mt)
                    #pragma unroll
                    for (int nt = 0; nt < 4; ++nt)
                        mma16816(acc[mt][nt], af[ks][mt], &bf[ks][nt >> 1][(nt & 1) * 2]);
        }
        __syncthreads();  // all stage reads done

        // prefetch next iteration's W chunks 0..2 (overlaps epilogue + barrier)
        #pragma unroll
        for (int pc = 0; pc < 3; ++pc) { load_W(smb + pc * STAGEB, pc, wbase, tid); cp_commit(); }

        // ---- combine k-halves: grp0 -> gsm, grp1 -> gsm2; single sync ----
        {
            float* gdst = grp ? gsm2 : gsm;
            #pragma unroll
            for (int mt = 0; mt < 2; ++mt)
                #pragma unroll
                for (int nt = 0; nt < 4; ++nt)
                    #pragma unroll
                    for (int r = 0; r < 4; ++r) {
                        int row = m0 + mt * 16 + (lane >> 2) + ((r & 2) ? 8 : 0);
                        int col = n0 + nt * 8 + ((lane & 3) << 1) + (r & 1);
                        gdst[row * 68 + col] = acc[mt][nt][r];
                    }
        }
        __syncthreads();

        // A backpressure: before overwriting ring slot t&3, layer1 must have consumed t-4
        if (isA && t >= 4) waitflag(&g_genB, (unsigned)(t - 3));

        // ---- cell epilogue: 64 batches x 16 hidden units (4 per thread) ----
        #pragma unroll
        for (int j = 0; j < 4; ++j) {
            int idx = tid + j * NTHR;
            int bb = idx >> 4, ul = idx & 15;
            int uglob = nct * 16 + ul;
            int s = bb * HH + uglob;
            float gi = gsm[bb * 68 + ul]      + gsm2[bb * 68 + ul]      + bp[ul];
            float gf = gsm[bb * 68 + 16 + ul] + gsm2[bb * 68 + 16 + ul] + bp[16 + ul];
            float gg = gsm[bb * 68 + 32 + ul] + gsm2[bb * 68 + 32 + ul] + bp[32 + ul];
            float go = gsm[bb * 68 + 48 + ul] + gsm2[bb * 68 + 48 + ul] + bp[48 + ul];
            float si = 1.f / (1.f + __expf(-gi));
            float sf = 1.f / (1.f + __expf(-gf));
            float so = 1.f / (1.f + __expf(-go));
            float tg = tanhf(gg);
            float cn = sf * cpre[j] + si * tg;
            float h  = so * tanhf(cn);
            if (gm == 0) {
                g_hf0[t & 3][s] = __float2half_rn(h);
            } else if (gm == 1) {
                g_h0[t & 3][s] = __float2half_rn(h);
                g_c0[t & 1][s] = cn;
            } else {
                size_t ob = ((size_t)bb * TT + t) * 2048 + (gm == 3 ? 1024 : 0) + uglob;
                out[ob]  = h;
                cout[ob] = cn;
                if (t == TT - 1) {
                    int o2 = bb * 2048 + (gm == 3 ? 1024 : 0) + uglob;
                    outL[o2]  = h;
                    coutL[o2] = cn;
                }
                if (gm == 3) {
                    g_h1[t & 1][s] = __float2half_rn(h);
                    g_c1[t & 1][s] = cn;
                }
            }
        }
        groupbar((unsigned)(t + 1), isA);
    }
    cp_wait0();   // drain leftover W prefetch before exit
}

// ---------------- launcher ----------------
extern "C" void kernel_launch(void* const* d_in, const int* in_sizes, int n_in,
                              void* d_out, int out_size) {
    (void)in_sizes; (void)n_in; (void)out_size;
    const float* x     = (const float*)d_in[0];
    const float* Wih_f = (const float*)d_in[1];
    const float* Whh_f = (const float*)d_in[2];
    const float* bih_f = (const float*)d_in[3];
    const float* bhh_f = (const float*)d_in[4];
    const float* Wih_b = (const float*)d_in[5];
    const float* Whh_b = (const float*)d_in[6];
    const float* bih_b = (const float*)d_in[7];
    const float* bhh_b = (const float*)d_in[8];

    cudaFuncSetAttribute(k_lstm, cudaFuncAttributeMaxDynamicSharedMemorySize, SMEM_BYTES);

    k_prep<<<8192, 256>>>(x, Wih_f, Whh_f, bih_f, bhh_f, Wih_b, Whh_b, bih_b, bhh_b);
    k_lstm<<<NB, NTHR, SMEM_BYTES>>>((float*)d_out);
}